// round 15
// baseline (speedup 1.0000x reference)
#include <cuda_runtime.h>
#include <cuda_bf16.h>
#include <cuda_fp16.h>
#include <stdint.h>

#define BB 16
#define LLEN 2048
#define DD 64
#define TQ 128
#define NTH 256
#define STRIDE 144                  // smem row stride bytes (16B mult, conflict-free)
#define BUFB (64 * STRIDE)          // one 64-row fp16 tile = 9216 B

#define OFF_V 0                     // V double buffer (fp16) = 2*9216
#define OFF_K (2 * BUFB)            // K double buffer (fp16) = 2*9216
#define SMEM_TOTAL (4 * BUFB)       // 36864 B

#define NEG_INF __int_as_float(0xff800000)
#define NROWSG (BB * LLEN)          // 32768 global q-rows
#define NELEM ((size_t)BB * LLEN * DD)   // 2M K/V elements

// scratch
__device__ __half2 g_h[(size_t)NROWSG * (LLEN / 2)];     // 134 MB: h = exp(s - M_s)
__device__ float   g_M[(size_t)128 * NROWSG];            // 16 MB: per-(slice,row) max
__device__ __half  g_kh[NELEM];                          // 4 MB: K in fp16
__device__ __half  g_vh[NELEM];                          // 4 MB: V in fp16

// ---------------- helpers ----------------
__device__ __forceinline__ uint32_t smem_u32(const void* p) {
    uint32_t a;
    asm("{ .reg .u64 t; cvta.to.shared.u64 t, %1; cvt.u32.u64 %0, t; }" : "=r"(a) : "l"(p));
    return a;
}
__device__ __forceinline__ void ldsm4(uint32_t a, uint32_t r[4]) {
    asm volatile("ldmatrix.sync.aligned.m8n8.x4.shared.b16 {%0,%1,%2,%3}, [%4];"
                 : "=r"(r[0]), "=r"(r[1]), "=r"(r[2]), "=r"(r[3]) : "r"(a));
}
__device__ __forceinline__ void ldsm4t(uint32_t a, uint32_t r[4]) {
    asm volatile("ldmatrix.sync.aligned.m8n8.x4.trans.shared.b16 {%0,%1,%2,%3}, [%4];"
                 : "=r"(r[0]), "=r"(r[1]), "=r"(r[2]), "=r"(r[3]) : "r"(a));
}
__device__ __forceinline__ void mma_f16(float* d, const uint32_t* a, uint32_t b0, uint32_t b1) {
    asm volatile("mma.sync.aligned.m16n8k16.row.col.f32.f16.f16.f32 "
                 "{%0,%1,%2,%3}, {%4,%5,%6,%7}, {%8,%9}, {%0,%1,%2,%3};"
                 : "+f"(d[0]), "+f"(d[1]), "+f"(d[2]), "+f"(d[3])
                 : "r"(a[0]), "r"(a[1]), "r"(a[2]), "r"(a[3]), "r"(b0), "r"(b1));
}
__device__ __forceinline__ uint32_t pack_h2(float a, float b) {
    __half2 h = __floats2half2_rn(a, b);
    return *reinterpret_cast<uint32_t*>(&h);
}
__device__ __forceinline__ void cpa16(uint32_t dst, const void* src) {
    asm volatile("cp.async.ca.shared.global [%0], [%1], 16;" :: "r"(dst), "l"(src));
}

// ============ prep: K and V fp32 -> fp16 ============
__global__ __launch_bounds__(256)
void prep_kernel(const float* __restrict__ kg, const float* __restrict__ vg)
{
    size_t idx = (size_t)blockIdx.x * 256 + threadIdx.x;   // float4 index
    float4 kv = reinterpret_cast<const float4*>(kg)[idx];
    reinterpret_cast<uint2*>(g_kh)[idx] =
        make_uint2(pack_h2(kv.x, kv.y), pack_h2(kv.z, kv.w));
    float4 vv = reinterpret_cast<const float4*>(vg)[idx];
    reinterpret_cast<uint2*>(g_vh)[idx] =
        make_uint2(pack_h2(vv.x, vv.y), pack_h2(vv.z, vv.w));
}

__global__ __launch_bounds__(NTH, 3)
void attn_mma_kernel(const float* __restrict__ qg,
                     const int* __restrict__ diag,
                     const int* __restrict__ maskb,
                     float* __restrict__ outp,
                     float* __restrict__ attn)
{
    extern __shared__ __align__(16) char smem[];
    const int tid  = threadIdx.x;
    const int wid  = tid >> 5;
    const int lane = tid & 31;
    const int qt   = lane & 3;
    const int b    = blockIdx.y;
    const int q0   = blockIdx.x * TQ;

    const uint32_t sb = smem_u32(smem);
    const char* ks_base = reinterpret_cast<const char*>(g_kh) + (size_t)b * LLEN * DD * 2;
    const char* vs_base = reinterpret_cast<const char*>(g_vh) + (size_t)b * LLEN * DD * 2;

    const int r0l = wid * 16 + (lane >> 2);          // this thread's row0 (row1 = +8)
    const size_t g0 = (size_t)b * LLEN + q0 + r0l;
    const int* m0p = maskb + g0 * LLEN;
    const int* m1p = m0p + (size_t)8 * LLEN;
    const int* d0p = diag + g0 * LLEN;
    const int* d1p = d0p + (size_t)8 * LLEN;
    float* a0p = attn + g0 * LLEN;
    float* a1p = a0p + (size_t)8 * LLEN;
    __half2* h0p = g_h + g0 * (LLEN / 2);
    __half2* h1p = h0p + (size_t)8 * (LLEN / 2);

    // per-thread 16B chunk offsets for cp.async tile copies (2 chunks/thread)
    int csrc[2], cdst[2];
    #pragma unroll
    for (int i = 0; i < 2; ++i) {
        int c = tid + i * 256;
        csrc[i] = (c >> 3) * 128 + (c & 7) * 16;
        cdst[i] = (c >> 3) * STRIDE + (c & 7) * 16;
    }

    // ---- Q fragments: fp16, scaled by 1/8, straight from global ----
    uint32_t qf[16];
    {
        const float* q0p = qg + g0 * DD;
        const float* q1p = q0p + 8 * DD;
        #pragma unroll
        for (int kc = 0; kc < 4; ++kc) {
            const int c = kc * 16 + qt * 2;
            float2 x0 = *reinterpret_cast<const float2*>(q0p + c);
            float2 x1 = *reinterpret_cast<const float2*>(q1p + c);
            float2 x2 = *reinterpret_cast<const float2*>(q0p + c + 8);
            float2 x3 = *reinterpret_cast<const float2*>(q1p + c + 8);
            qf[4 * kc + 0] = pack_h2(x0.x * 0.125f, x0.y * 0.125f);
            qf[4 * kc + 1] = pack_h2(x1.x * 0.125f, x1.y * 0.125f);
            qf[4 * kc + 2] = pack_h2(x2.x * 0.125f, x2.y * 0.125f);
            qf[4 * kc + 3] = pack_h2(x3.x * 0.125f, x3.y * 0.125f);
        }
    }

    // ldmatrix per-lane address components (relative to buffer base)
    const uint32_t boff = (uint32_t)(((((lane >> 4) & 1) * 8) + (lane & 7)) * STRIDE
                                     + ((lane >> 3) & 1) * 16);
    const uint32_t voff = (uint32_t)(((((lane >> 3) & 1) * 8) + (lane & 7)) * STRIDE
                                     + ((lane >> 4) & 1) * 16);

    float m0 = -3.0e38f, m1 = -3.0e38f, l0 = 0.0f, l1 = 0.0f;

    // prologue pass 1: issue K tile 0 into buffer 0
    #pragma unroll
    for (int i = 0; i < 2; ++i)
        cpa16(sb + OFF_K + cdst[i], ks_base + csrc[i]);
    asm volatile("cp.async.commit_group;" ::: "memory");

    // ============ PASS 1: S = QK^T (fp16), masks, h(fp16)+M_s, stats ============
    for (int kt = 0; kt < 32; ++kt) {
        const int k0 = kt * 64;
        const int pb = kt & 1;

        __syncthreads();                 // readers of tile kt-1 (buf pb^1) done
        if (kt + 1 < 32) {
            const size_t nb = (size_t)(k0 + 64) * 128;
            #pragma unroll
            for (int i = 0; i < 2; ++i)
                cpa16(sb + OFF_K + (pb ^ 1) * BUFB + cdst[i], ks_base + nb + csrc[i]);
        }
        asm volatile("cp.async.commit_group;" ::: "memory");
        asm volatile("cp.async.wait_group 1;" ::: "memory");   // tile kt landed
        __syncthreads();                 // visible to all threads

        const uint32_t k_a = sb + OFF_K + pb * BUFB + boff;

        #pragma unroll
        for (int p = 0; p < 4; ++p) {
            // masks for this slice (loaded up-front; latency hidden by occupancy)
            int2 M0[2], D0[2], M1[2], D1[2];
            #pragma unroll
            for (int j = 0; j < 2; ++j) {
                const int cb = k0 + (2 * p + j) * 8 + qt * 2;
                M0[j] = __ldcs(reinterpret_cast<const int2*>(m0p + cb));
                D0[j] = __ldcs(reinterpret_cast<const int2*>(d0p + cb));
                M1[j] = __ldcs(reinterpret_cast<const int2*>(m1p + cb));
                D1[j] = __ldcs(reinterpret_cast<const int2*>(d1p + cb));
            }

            // QK MMA slice p: 16 S-columns, single fp16 term
            float acc[2][4];
            #pragma unroll
            for (int j = 0; j < 2; ++j)
                #pragma unroll
                for (int i = 0; i < 4; ++i) acc[j][i] = 0.0f;
            #pragma unroll
            for (int kc = 0; kc < 4; ++kc) {
                uint32_t k4[4];
                ldsm4(k_a + p * 16 * STRIDE + kc * 32, k4);
                mma_f16(acc[0], qf + 4 * kc, k4[0], k4[1]);
                mma_f16(acc[1], qf + 4 * kc, k4[2], k4[3]);
            }

            float smax0 = -3.0e38f, smax1 = -3.0e38f;
            #pragma unroll
            for (int j = 0; j < 2; ++j) {
                float s0 = acc[j][0], s1 = acc[j][1];
                float s2 = acc[j][2], s3 = acc[j][3];
                if (M0[j].x)      s0 = NEG_INF;
                if (D0[j].x == 0) s0 = -1.0e32f;
                if (M0[j].y)      s1 = NEG_INF;
                if (D0[j].y == 0) s1 = -1.0e32f;
                if (M1[j].x)      s2 = NEG_INF;
                if (D1[j].x == 0) s2 = -1.0e32f;
                if (M1[j].y)      s3 = NEG_INF;
                if (D1[j].y == 0) s3 = -1.0e32f;
                acc[j][0] = s0; acc[j][1] = s1; acc[j][2] = s2; acc[j][3] = s3;
                smax0 = fmaxf(smax0, fmaxf(s0, s1));
                smax1 = fmaxf(smax1, fmaxf(s2, s3));
            }
            smax0 = fmaxf(smax0, __shfl_xor_sync(0xffffffffu, smax0, 1));
            smax0 = fmaxf(smax0, __shfl_xor_sync(0xffffffffu, smax0, 2));
            smax1 = fmaxf(smax1, __shfl_xor_sync(0xffffffffu, smax1, 1));
            smax1 = fmaxf(smax1, __shfl_xor_sync(0xffffffffu, smax1, 2));
            const float mn0 = fmaxf(m0, smax0);
            const float mn1 = fmaxf(m1, smax1);

            float h00 = __expf(acc[0][0] - mn0), h01 = __expf(acc[0][1] - mn0);
            float h02 = __expf(acc[1][0] - mn0), h03 = __expf(acc[1][1] - mn0);
            float h10 = __expf(acc[0][2] - mn1), h11 = __expf(acc[0][3] - mn1);
            float h12 = __expf(acc[1][2] - mn1), h13 = __expf(acc[1][3] - mn1);

            const int cb0 = k0 + (2 * p) * 8 + qt * 2;
            const int cb1 = cb0 + 8;
            __stcs(h0p + (cb0 >> 1), __floats2half2_rn(h00, h01));
            __stcs(h0p + (cb1 >> 1), __floats2half2_rn(h02, h03));
            __stcs(h1p + (cb0 >> 1), __floats2half2_rn(h10, h11));
            __stcs(h1p + (cb1 >> 1), __floats2half2_rn(h12, h13));
            if (qt == 0) {
                const size_t ms = (size_t)(kt * 4 + p) * NROWSG;
                g_M[ms + g0]     = mn0;
                g_M[ms + g0 + 8] = mn1;
            }

            float e0 = h00 + h01 + h02 + h03;
            float e1 = h10 + h11 + h12 + h13;
            e0 += __shfl_xor_sync(0xffffffffu, e0, 1);
            e0 += __shfl_xor_sync(0xffffffffu, e0, 2);
            e1 += __shfl_xor_sync(0xffffffffu, e1, 1);
            e1 += __shfl_xor_sync(0xffffffffu, e1, 2);
            l0 = l0 * __expf(m0 - mn0) + e0;  m0 = mn0;
            l1 = l1 * __expf(m1 - mn1) + e1;  m1 = mn1;
        }
    }

    const float rinv0 = 1.0f / l0;
    const float rinv1 = 1.0f / l1;

    float oacc[8][4];
    #pragma unroll
    for (int nt = 0; nt < 8; ++nt)
        #pragma unroll
        for (int i = 0; i < 4; ++i) oacc[nt][i] = 0.0f;

    // prologue pass 2: issue V tile 31 (reverse walk) into its parity buffer
    {
        const size_t nb = (size_t)(31 * 64) * 128;
        #pragma unroll
        for (int i = 0; i < 2; ++i)
            cpa16(sb + OFF_V + (31 & 1) * BUFB + cdst[i], vs_base + nb + csrc[i]);
    }
    asm volatile("cp.async.commit_group;" ::: "memory");

    // ============ PASS 2 (REVERSE k-tiles; h written last is L2-hot) ============
    for (int it = 0; it < 32; ++it) {
        const int kt = 31 - it;
        const int k0 = kt * 64;
        const int pb = kt & 1;

        // prefetch first h slice for this tile (global, pre-barrier)
        uint32_t Hb[2][4];
        float Mb0[2], Mb1[2];
        {
            const int cA = k0 + qt * 2;
            Hb[0][0] = __ldcs(reinterpret_cast<const uint32_t*>(h0p + (cA >> 1)));
            Hb[0][1] = __ldcs(reinterpret_cast<const uint32_t*>(h0p + ((cA + 8) >> 1)));
            Hb[0][2] = __ldcs(reinterpret_cast<const uint32_t*>(h1p + (cA >> 1)));
            Hb[0][3] = __ldcs(reinterpret_cast<const uint32_t*>(h1p + ((cA + 8) >> 1)));
            const size_t ms = (size_t)(kt * 4) * NROWSG;
            Mb0[0] = __ldcs(&g_M[ms + g0]);
            Mb1[0] = __ldcs(&g_M[ms + g0 + 8]);
        }

        __syncthreads();                 // readers of previous V tile done
        if (kt > 0) {
            const size_t nb = (size_t)(k0 - 64) * 128;
            #pragma unroll
            for (int i = 0; i < 2; ++i)
                cpa16(sb + OFF_V + (pb ^ 1) * BUFB + cdst[i], vs_base + nb + csrc[i]);
        }
        asm volatile("cp.async.commit_group;" ::: "memory");
        asm volatile("cp.async.wait_group 1;" ::: "memory");   // V tile kt landed
        __syncthreads();

        const uint32_t v_a = sb + OFF_V + pb * BUFB + voff;

        #pragma unroll
        for (int kc2 = 0; kc2 < 4; ++kc2) {
            const int cur = kc2 & 1;
            if (kc2 < 3) {
                const int cA = k0 + (kc2 + 1) * 16 + qt * 2;
                Hb[cur ^ 1][0] = __ldcs(reinterpret_cast<const uint32_t*>(h0p + (cA >> 1)));
                Hb[cur ^ 1][1] = __ldcs(reinterpret_cast<const uint32_t*>(h0p + ((cA + 8) >> 1)));
                Hb[cur ^ 1][2] = __ldcs(reinterpret_cast<const uint32_t*>(h1p + (cA >> 1)));
                Hb[cur ^ 1][3] = __ldcs(reinterpret_cast<const uint32_t*>(h1p + ((cA + 8) >> 1)));
                const size_t ms = (size_t)(kt * 4 + kc2 + 1) * NROWSG;
                Mb0[cur ^ 1] = __ldcs(&g_M[ms + g0]);
                Mb1[cur ^ 1] = __ldcs(&g_M[ms + g0 + 8]);
            }

            const float f0 = __expf(Mb0[cur] - m0) * rinv0;
            const float f1 = __expf(Mb1[cur] - m1) * rinv1;

            const int cA = k0 + kc2 * 16 + qt * 2;
            float2 xa = __half22float2(*reinterpret_cast<const __half2*>(&Hb[cur][0]));
            float2 xb = __half22float2(*reinterpret_cast<const __half2*>(&Hb[cur][1]));
            float2 xc = __half22float2(*reinterpret_cast<const __half2*>(&Hb[cur][2]));
            float2 xd = __half22float2(*reinterpret_cast<const __half2*>(&Hb[cur][3]));
            float p00 = xa.x * f0, p01 = xa.y * f0;
            float p02 = xb.x * f0, p03 = xb.y * f0;
            float p10 = xc.x * f1, p11 = xc.y * f1;
            float p12 = xd.x * f1, p13 = xd.y * f1;
            __stcs(reinterpret_cast<float2*>(a0p + cA),     make_float2(p00, p01));
            __stcs(reinterpret_cast<float2*>(a0p + cA + 8), make_float2(p02, p03));
            __stcs(reinterpret_cast<float2*>(a1p + cA),     make_float2(p10, p11));
            __stcs(reinterpret_cast<float2*>(a1p + cA + 8), make_float2(p12, p13));

            uint32_t pf[4];
            pf[0] = pack_h2(p00, p01);
            pf[1] = pack_h2(p10, p11);
            pf[2] = pack_h2(p02, p03);
            pf[3] = pack_h2(p12, p13);

            #pragma unroll
            for (int p = 0; p < 4; ++p) {
                uint32_t v4[4];
                ldsm4t(v_a + kc2 * 16 * STRIDE + p * 32, v4);
                mma_f16(oacc[2 * p],     pf, v4[0], v4[1]);
                mma_f16(oacc[2 * p + 1], pf, v4[2], v4[3]);
            }
        }
    }

    // ---- write output ----
    float* o0 = outp + g0 * DD;
    float* o1 = o0 + (size_t)8 * DD;
    #pragma unroll
    for (int nt = 0; nt < 8; ++nt) {
        const int cb = nt * 8 + qt * 2;
        __stcs(reinterpret_cast<float2*>(o0 + cb), make_float2(oacc[nt][0], oacc[nt][1]));
        __stcs(reinterpret_cast<float2*>(o1 + cb), make_float2(oacc[nt][2], oacc[nt][3]));
    }
}

extern "C" void kernel_launch(void* const* d_in, const int* in_sizes, int n_in,
                              void* d_out, int out_size)
{
    const float* q    = (const float*)d_in[0];
    const float* k    = (const float*)d_in[1];
    const float* v    = (const float*)d_in[2];
    const int*   diag = (const int*)d_in[3];
    const int*   mask = (const int*)d_in[4];

    float* out  = (float*)d_out;                     // [B, L, D]
    float* attn = out + (size_t)BB * LLEN * DD;      // [B, L, L]

    prep_kernel<<<(unsigned)(NELEM / 4 / 256), 256>>>(k, v);

    cudaFuncSetAttribute(attn_mma_kernel,
                         cudaFuncAttributeMaxDynamicSharedMemorySize, SMEM_TOTAL);
    dim3 grid(LLEN / TQ, BB);
    attn_mma_kernel<<<grid, NTH, SMEM_TOTAL>>>(q, diag, mask, out, attn);
}

// round 16
// speedup vs baseline: 1.1531x; 1.1531x over previous
#include <cuda_runtime.h>
#include <cuda_bf16.h>
#include <cuda_fp16.h>
#include <stdint.h>

#define BB 16
#define LLEN 2048
#define DD 64
#define TQ 128
#define NTH 256
#define STRIDE 144                  // smem row stride bytes (16B mult, conflict-free)
#define BUFB (64 * STRIDE)          // one 64-row fp16 tile = 9216 B

#define OFF_V 0                     // V double buffer (fp16) = 2*9216
#define OFF_K (2 * BUFB)            // K double buffer (fp16) = 2*9216
#define SMEM_TOTAL (4 * BUFB)       // 36864 B

#define NEG_INF __int_as_float(0xff800000)
#define NROWSG (BB * LLEN)          // 32768 global q-rows
#define NELEM ((size_t)BB * LLEN * DD)   // 2M K/V elements

// scratch
__device__ __half2 g_h[(size_t)NROWSG * (LLEN / 2)];     // 134 MB: h = exp(s - M_s)
__device__ float   g_M[(size_t)128 * NROWSG];            // 16 MB: per-(slice,row) max
__device__ __half  g_kh[NELEM];                          // 4 MB: K in fp16
__device__ __half  g_vh[NELEM];                          // 4 MB: V in fp16

// ---------------- helpers ----------------
__device__ __forceinline__ uint32_t smem_u32(const void* p) {
    uint32_t a;
    asm("{ .reg .u64 t; cvta.to.shared.u64 t, %1; cvt.u32.u64 %0, t; }" : "=r"(a) : "l"(p));
    return a;
}
__device__ __forceinline__ void ldsm4(uint32_t a, uint32_t r[4]) {
    asm volatile("ldmatrix.sync.aligned.m8n8.x4.shared.b16 {%0,%1,%2,%3}, [%4];"
                 : "=r"(r[0]), "=r"(r[1]), "=r"(r[2]), "=r"(r[3]) : "r"(a));
}
__device__ __forceinline__ void ldsm4t(uint32_t a, uint32_t r[4]) {
    asm volatile("ldmatrix.sync.aligned.m8n8.x4.trans.shared.b16 {%0,%1,%2,%3}, [%4];"
                 : "=r"(r[0]), "=r"(r[1]), "=r"(r[2]), "=r"(r[3]) : "r"(a));
}
__device__ __forceinline__ void mma_f16(float* d, const uint32_t* a, uint32_t b0, uint32_t b1) {
    asm volatile("mma.sync.aligned.m16n8k16.row.col.f32.f16.f16.f32 "
                 "{%0,%1,%2,%3}, {%4,%5,%6,%7}, {%8,%9}, {%0,%1,%2,%3};"
                 : "+f"(d[0]), "+f"(d[1]), "+f"(d[2]), "+f"(d[3])
                 : "r"(a[0]), "r"(a[1]), "r"(a[2]), "r"(a[3]), "r"(b0), "r"(b1));
}
__device__ __forceinline__ uint32_t pack_h2(float a, float b) {
    __half2 h = __floats2half2_rn(a, b);
    return *reinterpret_cast<uint32_t*>(&h);
}
__device__ __forceinline__ void cpa16(uint32_t dst, const void* src) {
    asm volatile("cp.async.ca.shared.global [%0], [%1], 16;" :: "r"(dst), "l"(src));
}

// ============ prep: K and V fp32 -> fp16 ============
__global__ __launch_bounds__(256)
void prep_kernel(const float* __restrict__ kg, const float* __restrict__ vg)
{
    size_t idx = (size_t)blockIdx.x * 256 + threadIdx.x;   // float4 index
    float4 kv = reinterpret_cast<const float4*>(kg)[idx];
    reinterpret_cast<uint2*>(g_kh)[idx] =
        make_uint2(pack_h2(kv.x, kv.y), pack_h2(kv.z, kv.w));
    float4 vv = reinterpret_cast<const float4*>(vg)[idx];
    reinterpret_cast<uint2*>(g_vh)[idx] =
        make_uint2(pack_h2(vv.x, vv.y), pack_h2(vv.z, vv.w));
}

__global__ __launch_bounds__(NTH, 2)
void attn_mma_kernel(const float* __restrict__ qg,
                     const int* __restrict__ diag,
                     const int* __restrict__ maskb,
                     float* __restrict__ outp,
                     float* __restrict__ attn)
{
    extern __shared__ __align__(16) char smem[];
    const int tid  = threadIdx.x;
    const int wid  = tid >> 5;
    const int lane = tid & 31;
    const int qt   = lane & 3;
    const int b    = blockIdx.y;
    const int q0   = blockIdx.x * TQ;

    const uint32_t sb = smem_u32(smem);
    const char* ks_base = reinterpret_cast<const char*>(g_kh) + (size_t)b * LLEN * DD * 2;
    const char* vs_base = reinterpret_cast<const char*>(g_vh) + (size_t)b * LLEN * DD * 2;

    const int r0l = wid * 16 + (lane >> 2);          // this thread's row0 (row1 = +8)
    const size_t g0 = (size_t)b * LLEN + q0 + r0l;
    const int* m0p = maskb + g0 * LLEN;
    const int* m1p = m0p + (size_t)8 * LLEN;
    const int* d0p = diag + g0 * LLEN;
    const int* d1p = d0p + (size_t)8 * LLEN;
    float* a0p = attn + g0 * LLEN;
    float* a1p = a0p + (size_t)8 * LLEN;
    __half2* h0p = g_h + g0 * (LLEN / 2);
    __half2* h1p = h0p + (size_t)8 * (LLEN / 2);

    // per-thread 16B chunk offsets for cp.async tile copies (2 chunks/thread)
    int csrc[2], cdst[2];
    #pragma unroll
    for (int i = 0; i < 2; ++i) {
        int c = tid + i * 256;
        csrc[i] = (c >> 3) * 128 + (c & 7) * 16;
        cdst[i] = (c >> 3) * STRIDE + (c & 7) * 16;
    }

    // ---- Q fragments: fp16, scaled by 1/8, straight from global ----
    uint32_t qf[16];
    {
        const float* q0p = qg + g0 * DD;
        const float* q1p = q0p + 8 * DD;
        #pragma unroll
        for (int kc = 0; kc < 4; ++kc) {
            const int c = kc * 16 + qt * 2;
            float2 x0 = *reinterpret_cast<const float2*>(q0p + c);
            float2 x1 = *reinterpret_cast<const float2*>(q1p + c);
            float2 x2 = *reinterpret_cast<const float2*>(q0p + c + 8);
            float2 x3 = *reinterpret_cast<const float2*>(q1p + c + 8);
            qf[4 * kc + 0] = pack_h2(x0.x * 0.125f, x0.y * 0.125f);
            qf[4 * kc + 1] = pack_h2(x1.x * 0.125f, x1.y * 0.125f);
            qf[4 * kc + 2] = pack_h2(x2.x * 0.125f, x2.y * 0.125f);
            qf[4 * kc + 3] = pack_h2(x3.x * 0.125f, x3.y * 0.125f);
        }
    }

    // ldmatrix per-lane address components (relative to buffer base)
    const uint32_t boff = (uint32_t)(((((lane >> 4) & 1) * 8) + (lane & 7)) * STRIDE
                                     + ((lane >> 3) & 1) * 16);
    const uint32_t voff = (uint32_t)(((((lane >> 3) & 1) * 8) + (lane & 7)) * STRIDE
                                     + ((lane >> 4) & 1) * 16);

    float m0 = -3.0e38f, m1 = -3.0e38f, l0 = 0.0f, l1 = 0.0f;

    // prologue pass 1: issue K tile 0 into buffer 0
    #pragma unroll
    for (int i = 0; i < 2; ++i)
        cpa16(sb + OFF_K + cdst[i], ks_base + csrc[i]);
    asm volatile("cp.async.commit_group;" ::: "memory");

    // ============ PASS 1: S = QK^T (fp16), masks, h(fp16)+M_s, stats ============
    for (int kt = 0; kt < 32; ++kt) {
        const int k0 = kt * 64;
        const int pb = kt & 1;

        __syncthreads();                 // readers of tile kt-1 (buf pb^1) done
        if (kt + 1 < 32) {
            const size_t nb = (size_t)(k0 + 64) * 128;
            #pragma unroll
            for (int i = 0; i < 2; ++i)
                cpa16(sb + OFF_K + (pb ^ 1) * BUFB + cdst[i], ks_base + nb + csrc[i]);
        }
        asm volatile("cp.async.commit_group;" ::: "memory");
        asm volatile("cp.async.wait_group 1;" ::: "memory");   // tile kt landed
        __syncthreads();                 // visible to all threads

        const uint32_t k_a = sb + OFF_K + pb * BUFB + boff;

        // mask slice double buffers: [buf][row][j]
        int2 Mb[2][2][2], Db[2][2][2];
        #pragma unroll
        for (int j = 0; j < 2; ++j) {
            const int cb = k0 + j * 8 + qt * 2;
            Mb[0][0][j] = __ldcs(reinterpret_cast<const int2*>(m0p + cb));
            Db[0][0][j] = __ldcs(reinterpret_cast<const int2*>(d0p + cb));
            Mb[0][1][j] = __ldcs(reinterpret_cast<const int2*>(m1p + cb));
            Db[0][1][j] = __ldcs(reinterpret_cast<const int2*>(d1p + cb));
        }

        #pragma unroll
        for (int p = 0; p < 4; ++p) {
            const int cur = p & 1;
            if (p < 3) {
                #pragma unroll
                for (int j = 0; j < 2; ++j) {
                    const int cb = k0 + (2 * (p + 1) + j) * 8 + qt * 2;
                    Mb[cur ^ 1][0][j] = __ldcs(reinterpret_cast<const int2*>(m0p + cb));
                    Db[cur ^ 1][0][j] = __ldcs(reinterpret_cast<const int2*>(d0p + cb));
                    Mb[cur ^ 1][1][j] = __ldcs(reinterpret_cast<const int2*>(m1p + cb));
                    Db[cur ^ 1][1][j] = __ldcs(reinterpret_cast<const int2*>(d1p + cb));
                }
            }

            // QK MMA slice p: 16 S-columns, single fp16 term
            float acc[2][4];
            #pragma unroll
            for (int j = 0; j < 2; ++j)
                #pragma unroll
                for (int i = 0; i < 4; ++i) acc[j][i] = 0.0f;
            #pragma unroll
            for (int kc = 0; kc < 4; ++kc) {
                uint32_t k4[4];
                ldsm4(k_a + p * 16 * STRIDE + kc * 32, k4);
                mma_f16(acc[0], qf + 4 * kc, k4[0], k4[1]);
                mma_f16(acc[1], qf + 4 * kc, k4[2], k4[3]);
            }

            float smax0 = -3.0e38f, smax1 = -3.0e38f;
            #pragma unroll
            for (int j = 0; j < 2; ++j) {
                float s0 = acc[j][0], s1 = acc[j][1];
                float s2 = acc[j][2], s3 = acc[j][3];
                if (Mb[cur][0][j].x)      s0 = NEG_INF;
                if (Db[cur][0][j].x == 0) s0 = -1.0e32f;
                if (Mb[cur][0][j].y)      s1 = NEG_INF;
                if (Db[cur][0][j].y == 0) s1 = -1.0e32f;
                if (Mb[cur][1][j].x)      s2 = NEG_INF;
                if (Db[cur][1][j].x == 0) s2 = -1.0e32f;
                if (Mb[cur][1][j].y)      s3 = NEG_INF;
                if (Db[cur][1][j].y == 0) s3 = -1.0e32f;
                acc[j][0] = s0; acc[j][1] = s1; acc[j][2] = s2; acc[j][3] = s3;
                smax0 = fmaxf(smax0, fmaxf(s0, s1));
                smax1 = fmaxf(smax1, fmaxf(s2, s3));
            }
            smax0 = fmaxf(smax0, __shfl_xor_sync(0xffffffffu, smax0, 1));
            smax0 = fmaxf(smax0, __shfl_xor_sync(0xffffffffu, smax0, 2));
            smax1 = fmaxf(smax1, __shfl_xor_sync(0xffffffffu, smax1, 1));
            smax1 = fmaxf(smax1, __shfl_xor_sync(0xffffffffu, smax1, 2));
            const float mn0 = fmaxf(m0, smax0);
            const float mn1 = fmaxf(m1, smax1);

            float h00 = __expf(acc[0][0] - mn0), h01 = __expf(acc[0][1] - mn0);
            float h02 = __expf(acc[1][0] - mn0), h03 = __expf(acc[1][1] - mn0);
            float h10 = __expf(acc[0][2] - mn1), h11 = __expf(acc[0][3] - mn1);
            float h12 = __expf(acc[1][2] - mn1), h13 = __expf(acc[1][3] - mn1);

            const int cb0 = k0 + (2 * p) * 8 + qt * 2;
            const int cb1 = cb0 + 8;
            // h is re-read in pass 2: keep it L2-resident (cg, NOT streaming)
            __stcg(h0p + (cb0 >> 1), __floats2half2_rn(h00, h01));
            __stcg(h0p + (cb1 >> 1), __floats2half2_rn(h02, h03));
            __stcg(h1p + (cb0 >> 1), __floats2half2_rn(h10, h11));
            __stcg(h1p + (cb1 >> 1), __floats2half2_rn(h12, h13));
            if (qt == 0) {
                const size_t ms = (size_t)(kt * 4 + p) * NROWSG;
                __stcg(&g_M[ms + g0],     mn0);
                __stcg(&g_M[ms + g0 + 8], mn1);
            }

            float e0 = h00 + h01 + h02 + h03;
            float e1 = h10 + h11 + h12 + h13;
            e0 += __shfl_xor_sync(0xffffffffu, e0, 1);
            e0 += __shfl_xor_sync(0xffffffffu, e0, 2);
            e1 += __shfl_xor_sync(0xffffffffu, e1, 1);
            e1 += __shfl_xor_sync(0xffffffffu, e1, 2);
            l0 = l0 * __expf(m0 - mn0) + e0;  m0 = mn0;
            l1 = l1 * __expf(m1 - mn1) + e1;  m1 = mn1;
        }
    }

    const float rinv0 = 1.0f / l0;
    const float rinv1 = 1.0f / l1;

    float oacc[8][4];
    #pragma unroll
    for (int nt = 0; nt < 8; ++nt)
        #pragma unroll
        for (int i = 0; i < 4; ++i) oacc[nt][i] = 0.0f;

    // prologue pass 2: issue V tile 31 (reverse walk) into its parity buffer
    {
        const size_t nb = (size_t)(31 * 64) * 128;
        #pragma unroll
        for (int i = 0; i < 2; ++i)
            cpa16(sb + OFF_V + (31 & 1) * BUFB + cdst[i], vs_base + nb + csrc[i]);
    }
    asm volatile("cp.async.commit_group;" ::: "memory");

    // ============ PASS 2 (REVERSE k-tiles: most recent h is L2-hot) ============
    for (int it = 0; it < 32; ++it) {
        const int kt = 31 - it;
        const int k0 = kt * 64;
        const int pb = kt & 1;

        // prefetch first h slice for this tile (global, pre-barrier)
        uint32_t Hb[2][4];
        float Mb0[2], Mb1[2];
        {
            const int cA = k0 + qt * 2;
            Hb[0][0] = __ldcg(reinterpret_cast<const uint32_t*>(h0p + (cA >> 1)));
            Hb[0][1] = __ldcg(reinterpret_cast<const uint32_t*>(h0p + ((cA + 8) >> 1)));
            Hb[0][2] = __ldcg(reinterpret_cast<const uint32_t*>(h1p + (cA >> 1)));
            Hb[0][3] = __ldcg(reinterpret_cast<const uint32_t*>(h1p + ((cA + 8) >> 1)));
            const size_t ms = (size_t)(kt * 4) * NROWSG;
            Mb0[0] = __ldcg(&g_M[ms + g0]);
            Mb1[0] = __ldcg(&g_M[ms + g0 + 8]);
        }

        __syncthreads();                 // readers of previous V tile done
        if (kt > 0) {
            const size_t nb = (size_t)(k0 - 64) * 128;
            #pragma unroll
            for (int i = 0; i < 2; ++i)
                cpa16(sb + OFF_V + (pb ^ 1) * BUFB + cdst[i], vs_base + nb + csrc[i]);
        }
        asm volatile("cp.async.commit_group;" ::: "memory");
        asm volatile("cp.async.wait_group 1;" ::: "memory");   // V tile kt landed
        __syncthreads();

        const uint32_t v_a = sb + OFF_V + pb * BUFB + voff;

        #pragma unroll
        for (int kc2 = 0; kc2 < 4; ++kc2) {
            const int cur = kc2 & 1;
            if (kc2 < 3) {
                const int cA = k0 + (kc2 + 1) * 16 + qt * 2;
                Hb[cur ^ 1][0] = __ldcg(reinterpret_cast<const uint32_t*>(h0p + (cA >> 1)));
                Hb[cur ^ 1][1] = __ldcg(reinterpret_cast<const uint32_t*>(h0p + ((cA + 8) >> 1)));
                Hb[cur ^ 1][2] = __ldcg(reinterpret_cast<const uint32_t*>(h1p + (cA >> 1)));
                Hb[cur ^ 1][3] = __ldcg(reinterpret_cast<const uint32_t*>(h1p + ((cA + 8) >> 1)));
                const size_t ms = (size_t)(kt * 4 + kc2 + 1) * NROWSG;
                Mb0[cur ^ 1] = __ldcg(&g_M[ms + g0]);
                Mb1[cur ^ 1] = __ldcg(&g_M[ms + g0 + 8]);
            }

            const float f0 = __expf(Mb0[cur] - m0) * rinv0;
            const float f1 = __expf(Mb1[cur] - m1) * rinv1;

            const int cA = k0 + kc2 * 16 + qt * 2;
            float2 xa = __half22float2(*reinterpret_cast<const __half2*>(&Hb[cur][0]));
            float2 xb = __half22float2(*reinterpret_cast<const __half2*>(&Hb[cur][1]));
            float2 xc = __half22float2(*reinterpret_cast<const __half2*>(&Hb[cur][2]));
            float2 xd = __half22float2(*reinterpret_cast<const __half2*>(&Hb[cur][3]));
            float p00 = xa.x * f0, p01 = xa.y * f0;
            float p02 = xb.x * f0, p03 = xb.y * f0;
            float p10 = xc.x * f1, p11 = xc.y * f1;
            float p12 = xd.x * f1, p13 = xd.y * f1;
            __stcs(reinterpret_cast<float2*>(a0p + cA),     make_float2(p00, p01));
            __stcs(reinterpret_cast<float2*>(a0p + cA + 8), make_float2(p02, p03));
            __stcs(reinterpret_cast<float2*>(a1p + cA),     make_float2(p10, p11));
            __stcs(reinterpret_cast<float2*>(a1p + cA + 8), make_float2(p12, p13));

            uint32_t pf[4];
            pf[0] = pack_h2(p00, p01);
            pf[1] = pack_h2(p10, p11);
            pf[2] = pack_h2(p02, p03);
            pf[3] = pack_h2(p12, p13);

            #pragma unroll
            for (int p = 0; p < 4; ++p) {
                uint32_t v4[4];
                ldsm4t(v_a + kc2 * 16 * STRIDE + p * 32, v4);
                mma_f16(oacc[2 * p],     pf, v4[0], v4[1]);
                mma_f16(oacc[2 * p + 1], pf, v4[2], v4[3]);
            }
        }
    }

    // ---- write output ----
    float* o0 = outp + g0 * DD;
    float* o1 = o0 + (size_t)8 * DD;
    #pragma unroll
    for (int nt = 0; nt < 8; ++nt) {
        const int cb = nt * 8 + qt * 2;
        __stcs(reinterpret_cast<float2*>(o0 + cb), make_float2(oacc[nt][0], oacc[nt][1]));
        __stcs(reinterpret_cast<float2*>(o1 + cb), make_float2(oacc[nt][2], oacc[nt][3]));
    }
}

extern "C" void kernel_launch(void* const* d_in, const int* in_sizes, int n_in,
                              void* d_out, int out_size)
{
    const float* q    = (const float*)d_in[0];
    const float* k    = (const float*)d_in[1];
    const float* v    = (const float*)d_in[2];
    const int*   diag = (const int*)d_in[3];
    const int*   mask = (const int*)d_in[4];

    float* out  = (float*)d_out;                     // [B, L, D]
    float* attn = out + (size_t)BB * LLEN * DD;      // [B, L, L]

    prep_kernel<<<(unsigned)(NELEM / 4 / 256), 256>>>(k, v);

    cudaFuncSetAttribute(attn_mma_kernel,
                         cudaFuncAttributeMaxDynamicSharedMemorySize, SMEM_TOTAL);
    dim3 grid(LLEN / TQ, BB);
    attn_mma_kernel<<<grid, NTH, SMEM_TOTAL>>>(q, diag, mask, out, attn);
}

// round 17
// speedup vs baseline: 1.4096x; 1.2225x over previous
#include <cuda_runtime.h>
#include <cuda_bf16.h>
#include <cuda_fp16.h>
#include <stdint.h>

#define BB 16
#define LLEN 2048
#define DD 64
#define TQ 128
#define NTH 256
#define STRIDE 144                  // smem row stride bytes (16B mult, conflict-free)
#define BUFB (64 * STRIDE)          // one 64-row fp16 tile = 9216 B

#define OFF_V 0                     // V double buffer (fp16) = 2*9216
#define OFF_K (2 * BUFB)            // K double buffer (fp16) = 2*9216
#define SMEM_TOTAL (4 * BUFB)       // 36864 B

#define NEG_INF __int_as_float(0xff800000)
#define NROWSG (BB * LLEN)          // 32768 global q-rows
#define NELEM ((size_t)BB * LLEN * DD)   // 2M K/V elements

// scratch
__device__ uint32_t g_pk[(size_t)32 * NROWSG * 4];   // 16.8 MB: packed mask bits
                                                     // word = (tile kt, row, qt); byte p = slice bits
__device__ __half  g_kh[NELEM];                      // 4 MB: K in fp16
__device__ __half  g_vh[NELEM];                      // 4 MB: V in fp16

// ---------------- helpers ----------------
__device__ __forceinline__ uint32_t smem_u32(const void* p) {
    uint32_t a;
    asm("{ .reg .u64 t; cvta.to.shared.u64 t, %1; cvt.u32.u64 %0, t; }" : "=r"(a) : "l"(p));
    return a;
}
__device__ __forceinline__ void ldsm4(uint32_t a, uint32_t r[4]) {
    asm volatile("ldmatrix.sync.aligned.m8n8.x4.shared.b16 {%0,%1,%2,%3}, [%4];"
                 : "=r"(r[0]), "=r"(r[1]), "=r"(r[2]), "=r"(r[3]) : "r"(a));
}
__device__ __forceinline__ void ldsm4t(uint32_t a, uint32_t r[4]) {
    asm volatile("ldmatrix.sync.aligned.m8n8.x4.trans.shared.b16 {%0,%1,%2,%3}, [%4];"
                 : "=r"(r[0]), "=r"(r[1]), "=r"(r[2]), "=r"(r[3]) : "r"(a));
}
__device__ __forceinline__ void mma_f16(float* d, const uint32_t* a, uint32_t b0, uint32_t b1) {
    asm volatile("mma.sync.aligned.m16n8k16.row.col.f32.f16.f16.f32 "
                 "{%0,%1,%2,%3}, {%4,%5,%6,%7}, {%8,%9}, {%0,%1,%2,%3};"
                 : "+f"(d[0]), "+f"(d[1]), "+f"(d[2]), "+f"(d[3])
                 : "r"(a[0]), "r"(a[1]), "r"(a[2]), "r"(a[3]), "r"(b0), "r"(b1));
}
__device__ __forceinline__ uint32_t pack_h2(float a, float b) {
    __half2 h = __floats2half2_rn(a, b);
    return *reinterpret_cast<uint32_t*>(&h);
}
__device__ __forceinline__ void cpa16(uint32_t dst, const void* src) {
    asm volatile("cp.async.ca.shared.global [%0], [%1], 16;" :: "r"(dst), "l"(src));
}
// apply one slice-byte's bits to 4 scores (c0,c1 = lo pair; c2,c3 = hi pair)
__device__ __forceinline__ void apply_byte(uint32_t by, float& s0, float& s1,
                                           float& s2, float& s3) {
    if (by & 1u)   s0 = NEG_INF;
    if (by & 2u)   s0 = -1.0e32f;
    if (by & 4u)   s1 = NEG_INF;
    if (by & 8u)   s1 = -1.0e32f;
    if (by & 16u)  s2 = NEG_INF;
    if (by & 32u)  s2 = -1.0e32f;
    if (by & 64u)  s3 = NEG_INF;
    if (by & 128u) s3 = -1.0e32f;
}

// ============ prep: K and V fp32 -> fp16 ============
__global__ __launch_bounds__(256)
void prep_kernel(const float* __restrict__ kg, const float* __restrict__ vg)
{
    size_t idx = (size_t)blockIdx.x * 256 + threadIdx.x;   // float4 index
    float4 kv = reinterpret_cast<const float4*>(kg)[idx];
    reinterpret_cast<uint2*>(g_kh)[idx] =
        make_uint2(pack_h2(kv.x, kv.y), pack_h2(kv.z, kv.w));
    float4 vv = reinterpret_cast<const float4*>(vg)[idx];
    reinterpret_cast<uint2*>(g_vh)[idx] =
        make_uint2(pack_h2(vv.x, vv.y), pack_h2(vv.z, vv.w));
}

__global__ __launch_bounds__(NTH, 2)
void attn_mma_kernel(const float* __restrict__ qg,
                     const int* __restrict__ diag,
                     const int* __restrict__ maskb,
                     float* __restrict__ outp,
                     float* __restrict__ attn)
{
    extern __shared__ __align__(16) char smem[];
    const int tid  = threadIdx.x;
    const int wid  = tid >> 5;
    const int lane = tid & 31;
    const int qt   = lane & 3;
    const int b    = blockIdx.y;
    const int q0   = blockIdx.x * TQ;

    const uint32_t sb = smem_u32(smem);
    const char* ks_base = reinterpret_cast<const char*>(g_kh) + (size_t)b * LLEN * DD * 2;
    const char* vs_base = reinterpret_cast<const char*>(g_vh) + (size_t)b * LLEN * DD * 2;

    const int r0l = wid * 16 + (lane >> 2);          // this thread's row0 (row1 = +8)
    const size_t g0 = (size_t)b * LLEN + q0 + r0l;
    const int* m0p = maskb + g0 * LLEN;
    const int* m1p = m0p + (size_t)8 * LLEN;
    const int* d0p = diag + g0 * LLEN;
    const int* d1p = d0p + (size_t)8 * LLEN;
    float* a0p = attn + g0 * LLEN;
    float* a1p = a0p + (size_t)8 * LLEN;

    // per-thread 16B chunk offsets for cp.async tile copies (2 chunks/thread)
    int csrc[2], cdst[2];
    #pragma unroll
    for (int i = 0; i < 2; ++i) {
        int c = tid + i * 256;
        csrc[i] = (c >> 3) * 128 + (c & 7) * 16;
        cdst[i] = (c >> 3) * STRIDE + (c & 7) * 16;
    }

    // ---- Q fragments: fp16, scaled by 1/8, straight from global ----
    uint32_t qf[16];
    {
        const float* q0p = qg + g0 * DD;
        const float* q1p = q0p + 8 * DD;
        #pragma unroll
        for (int kc = 0; kc < 4; ++kc) {
            const int c = kc * 16 + qt * 2;
            float2 x0 = *reinterpret_cast<const float2*>(q0p + c);
            float2 x1 = *reinterpret_cast<const float2*>(q1p + c);
            float2 x2 = *reinterpret_cast<const float2*>(q0p + c + 8);
            float2 x3 = *reinterpret_cast<const float2*>(q1p + c + 8);
            qf[4 * kc + 0] = pack_h2(x0.x * 0.125f, x0.y * 0.125f);
            qf[4 * kc + 1] = pack_h2(x1.x * 0.125f, x1.y * 0.125f);
            qf[4 * kc + 2] = pack_h2(x2.x * 0.125f, x2.y * 0.125f);
            qf[4 * kc + 3] = pack_h2(x3.x * 0.125f, x3.y * 0.125f);
        }
    }

    // ldmatrix per-lane address components (relative to buffer base)
    const uint32_t boff = (uint32_t)(((((lane >> 4) & 1) * 8) + (lane & 7)) * STRIDE
                                     + ((lane >> 3) & 1) * 16);
    const uint32_t voff = (uint32_t)(((((lane >> 3) & 1) * 8) + (lane & 7)) * STRIDE
                                     + ((lane >> 4) & 1) * 16);

    float m0 = -3.0e38f, m1 = -3.0e38f, l0 = 0.0f, l1 = 0.0f;

    // prologue pass 1: issue K tile 0 into buffer 0
    #pragma unroll
    for (int i = 0; i < 2; ++i)
        cpa16(sb + OFF_K + cdst[i], ks_base + csrc[i]);
    asm volatile("cp.async.commit_group;" ::: "memory");

    // ============ PASS 1: S = QK^T (fp16), masks -> packed bits, online stats ============
    for (int kt = 0; kt < 32; ++kt) {
        const int k0 = kt * 64;
        const int pb = kt & 1;

        __syncthreads();                 // readers of tile kt-1 (buf pb^1) done
        if (kt + 1 < 32) {
            const size_t nb = (size_t)(k0 + 64) * 128;
            #pragma unroll
            for (int i = 0; i < 2; ++i)
                cpa16(sb + OFF_K + (pb ^ 1) * BUFB + cdst[i], ks_base + nb + csrc[i]);
        }
        asm volatile("cp.async.commit_group;" ::: "memory");
        asm volatile("cp.async.wait_group 1;" ::: "memory");   // tile kt landed
        __syncthreads();                 // visible to all threads

        const uint32_t k_a = sb + OFF_K + pb * BUFB + boff;

        // mask slice double buffers: [buf][row][j]
        int2 Mb[2][2][2], Db[2][2][2];
        #pragma unroll
        for (int j = 0; j < 2; ++j) {
            const int cb = k0 + j * 8 + qt * 2;
            Mb[0][0][j] = __ldcs(reinterpret_cast<const int2*>(m0p + cb));
            Db[0][0][j] = __ldcs(reinterpret_cast<const int2*>(d0p + cb));
            Mb[0][1][j] = __ldcs(reinterpret_cast<const int2*>(m1p + cb));
            Db[0][1][j] = __ldcs(reinterpret_cast<const int2*>(d1p + cb));
        }

        uint32_t pkw0 = 0, pkw1 = 0;     // packed bytes for this tile (4 slices)

        #pragma unroll
        for (int p = 0; p < 4; ++p) {
            const int cur = p & 1;
            if (p < 3) {
                #pragma unroll
                for (int j = 0; j < 2; ++j) {
                    const int cb = k0 + (2 * (p + 1) + j) * 8 + qt * 2;
                    Mb[cur ^ 1][0][j] = __ldcs(reinterpret_cast<const int2*>(m0p + cb));
                    Db[cur ^ 1][0][j] = __ldcs(reinterpret_cast<const int2*>(d0p + cb));
                    Mb[cur ^ 1][1][j] = __ldcs(reinterpret_cast<const int2*>(m1p + cb));
                    Db[cur ^ 1][1][j] = __ldcs(reinterpret_cast<const int2*>(d1p + cb));
                }
            }

            // QK MMA slice p: 16 S-columns, single fp16 term
            float acc[2][4];
            #pragma unroll
            for (int j = 0; j < 2; ++j)
                #pragma unroll
                for (int i = 0; i < 4; ++i) acc[j][i] = 0.0f;
            #pragma unroll
            for (int kc = 0; kc < 4; ++kc) {
                uint32_t k4[4];
                ldsm4(k_a + p * 16 * STRIDE + kc * 32, k4);
                mma_f16(acc[0], qf + 4 * kc, k4[0], k4[1]);
                mma_f16(acc[1], qf + 4 * kc, k4[2], k4[3]);
            }

            // build packed bytes (bit order: c0m,c0d,c1m,c1d,c2m,c2d,c3m,c3d)
            uint32_t by0 = 0, by1 = 0;
            if (Mb[cur][0][0].x)      by0 |= 1u;
            if (Db[cur][0][0].x == 0) by0 |= 2u;
            if (Mb[cur][0][0].y)      by0 |= 4u;
            if (Db[cur][0][0].y == 0) by0 |= 8u;
            if (Mb[cur][0][1].x)      by0 |= 16u;
            if (Db[cur][0][1].x == 0) by0 |= 32u;
            if (Mb[cur][0][1].y)      by0 |= 64u;
            if (Db[cur][0][1].y == 0) by0 |= 128u;
            if (Mb[cur][1][0].x)      by1 |= 1u;
            if (Db[cur][1][0].x == 0) by1 |= 2u;
            if (Mb[cur][1][0].y)      by1 |= 4u;
            if (Db[cur][1][0].y == 0) by1 |= 8u;
            if (Mb[cur][1][1].x)      by1 |= 16u;
            if (Db[cur][1][1].x == 0) by1 |= 32u;
            if (Mb[cur][1][1].y)      by1 |= 64u;
            if (Db[cur][1][1].y == 0) by1 |= 128u;
            pkw0 |= by0 << (8 * p);
            pkw1 |= by1 << (8 * p);

            // apply masks (c0,c1 -> acc[0][0..1]/[2..3]; c2,c3 -> acc[1])
            apply_byte(by0, acc[0][0], acc[0][1], acc[1][0], acc[1][1]);
            apply_byte(by1, acc[0][2], acc[0][3], acc[1][2], acc[1][3]);

            float smax0 = fmaxf(fmaxf(acc[0][0], acc[0][1]), fmaxf(acc[1][0], acc[1][1]));
            float smax1 = fmaxf(fmaxf(acc[0][2], acc[0][3]), fmaxf(acc[1][2], acc[1][3]));
            smax0 = fmaxf(smax0, __shfl_xor_sync(0xffffffffu, smax0, 1));
            smax0 = fmaxf(smax0, __shfl_xor_sync(0xffffffffu, smax0, 2));
            smax1 = fmaxf(smax1, __shfl_xor_sync(0xffffffffu, smax1, 1));
            smax1 = fmaxf(smax1, __shfl_xor_sync(0xffffffffu, smax1, 2));
            const float mn0 = fmaxf(m0, smax0);
            const float mn1 = fmaxf(m1, smax1);

            float e0 = __expf(acc[0][0] - mn0) + __expf(acc[0][1] - mn0)
                     + __expf(acc[1][0] - mn0) + __expf(acc[1][1] - mn0);
            float e1 = __expf(acc[0][2] - mn1) + __expf(acc[0][3] - mn1)
                     + __expf(acc[1][2] - mn1) + __expf(acc[1][3] - mn1);
            e0 += __shfl_xor_sync(0xffffffffu, e0, 1);
            e0 += __shfl_xor_sync(0xffffffffu, e0, 2);
            e1 += __shfl_xor_sync(0xffffffffu, e1, 1);
            e1 += __shfl_xor_sync(0xffffffffu, e1, 2);
            l0 = l0 * __expf(m0 - mn0) + e0;  m0 = mn0;
            l1 = l1 * __expf(m1 - mn1) + e1;  m1 = mn1;
        }

        // one packed word per row per tile (re-read in pass 2 -> keep in L2)
        const size_t pkbase = ((size_t)kt * NROWSG + g0) * 4 + qt;
        __stcg(&g_pk[pkbase],          pkw0);
        __stcg(&g_pk[pkbase + 8 * 4],  pkw1);
    }

    const float rinv0 = 1.0f / l0;
    const float rinv1 = 1.0f / l1;

    float oacc[8][4];
    #pragma unroll
    for (int nt = 0; nt < 8; ++nt)
        #pragma unroll
        for (int i = 0; i < 4; ++i) oacc[nt][i] = 0.0f;

    // prologue pass 2: issue K tile 0 AND V tile 0 into buffer 0
    __syncthreads();                 // pass-1 K readers done before overwrite
    #pragma unroll
    for (int i = 0; i < 2; ++i) {
        cpa16(sb + OFF_K + cdst[i], ks_base + csrc[i]);
        cpa16(sb + OFF_V + cdst[i], vs_base + csrc[i]);
    }
    asm volatile("cp.async.commit_group;" ::: "memory");

    // ============ PASS 2: recompute S (bit-identical), probs, attn write, fp16 PV ============
    for (int kt = 0; kt < 32; ++kt) {
        const int k0 = kt * 64;
        const int pb = kt & 1;

        // packed mask words for this tile (tiny, L2-hot)
        const size_t pkbase = ((size_t)kt * NROWSG + g0) * 4 + qt;
        const uint32_t pk0 = __ldcg(&g_pk[pkbase]);
        const uint32_t pk1 = __ldcg(&g_pk[pkbase + 8 * 4]);

        __syncthreads();                 // readers of tile kt-1 done
        if (kt + 1 < 32) {
            const size_t nb = (size_t)(k0 + 64) * 128;
            #pragma unroll
            for (int i = 0; i < 2; ++i) {
                cpa16(sb + OFF_K + (pb ^ 1) * BUFB + cdst[i], ks_base + nb + csrc[i]);
                cpa16(sb + OFF_V + (pb ^ 1) * BUFB + cdst[i], vs_base + nb + csrc[i]);
            }
        }
        asm volatile("cp.async.commit_group;" ::: "memory");
        asm volatile("cp.async.wait_group 1;" ::: "memory");   // tile kt landed
        __syncthreads();

        const uint32_t k_a = sb + OFF_K + pb * BUFB + boff;
        const uint32_t v_a = sb + OFF_V + pb * BUFB + voff;

        #pragma unroll
        for (int p = 0; p < 4; ++p) {
            // recompute S slice (bit-identical to pass 1: same regs, same smem data)
            float acc[2][4];
            #pragma unroll
            for (int j = 0; j < 2; ++j)
                #pragma unroll
                for (int i = 0; i < 4; ++i) acc[j][i] = 0.0f;
            #pragma unroll
            for (int kc = 0; kc < 4; ++kc) {
                uint32_t k4[4];
                ldsm4(k_a + p * 16 * STRIDE + kc * 32, k4);
                mma_f16(acc[0], qf + 4 * kc, k4[0], k4[1]);
                mma_f16(acc[1], qf + 4 * kc, k4[2], k4[3]);
            }
            const uint32_t by0 = (pk0 >> (8 * p)) & 0xffu;
            const uint32_t by1 = (pk1 >> (8 * p)) & 0xffu;
            apply_byte(by0, acc[0][0], acc[0][1], acc[1][0], acc[1][1]);
            apply_byte(by1, acc[0][2], acc[0][3], acc[1][2], acc[1][3]);

            // final probs (fp32 exact path)
            float p00 = __expf(acc[0][0] - m0) * rinv0;
            float p01 = __expf(acc[0][1] - m0) * rinv0;
            float p02 = __expf(acc[1][0] - m0) * rinv0;
            float p03 = __expf(acc[1][1] - m0) * rinv0;
            float p10 = __expf(acc[0][2] - m1) * rinv1;
            float p11 = __expf(acc[0][3] - m1) * rinv1;
            float p12 = __expf(acc[1][2] - m1) * rinv1;
            float p13 = __expf(acc[1][3] - m1) * rinv1;

            const int cA = k0 + p * 16 + qt * 2;
            __stcs(reinterpret_cast<float2*>(a0p + cA),     make_float2(p00, p01));
            __stcs(reinterpret_cast<float2*>(a0p + cA + 8), make_float2(p02, p03));
            __stcs(reinterpret_cast<float2*>(a1p + cA),     make_float2(p10, p11));
            __stcs(reinterpret_cast<float2*>(a1p + cA + 8), make_float2(p12, p13));

            // fp16 P fragments (row0-klo, row1-klo, row0-khi, row1-khi)
            uint32_t pf[4];
            pf[0] = pack_h2(p00, p01);
            pf[1] = pack_h2(p10, p11);
            pf[2] = pack_h2(p02, p03);
            pf[3] = pack_h2(p12, p13);

            #pragma unroll
            for (int d = 0; d < 4; ++d) {
                uint32_t v4[4];
                ldsm4t(v_a + p * 16 * STRIDE + d * 32, v4);
                mma_f16(oacc[2 * d],     pf, v4[0], v4[1]);
                mma_f16(oacc[2 * d + 1], pf, v4[2], v4[3]);
            }
        }
    }

    // ---- write output ----
    float* o0 = outp + g0 * DD;
    float* o1 = o0 + (size_t)8 * DD;
    #pragma unroll
    for (int nt = 0; nt < 8; ++nt) {
        const int cb = nt * 8 + qt * 2;
        __stcs(reinterpret_cast<float2*>(o0 + cb), make_float2(oacc[nt][0], oacc[nt][1]));
        __stcs(reinterpret_cast<float2*>(o1 + cb), make_float2(oacc[nt][2], oacc[nt][3]));
    }
}

extern "C" void kernel_launch(void* const* d_in, const int* in_sizes, int n_in,
                              void* d_out, int out_size)
{
    const float* q    = (const float*)d_in[0];
    const float* k    = (const float*)d_in[1];
    const float* v    = (const float*)d_in[2];
    const int*   diag = (const int*)d_in[3];
    const int*   mask = (const int*)d_in[4];

    float* out  = (float*)d_out;                     // [B, L, D]
    float* attn = out + (size_t)BB * LLEN * DD;      // [B, L, L]

    prep_kernel<<<(unsigned)(NELEM / 4 / 256), 256>>>(k, v);

    cudaFuncSetAttribute(attn_mma_kernel,
                         cudaFuncAttributeMaxDynamicSharedMemorySize, SMEM_TOTAL);
    dim3 grid(LLEN / TQ, BB);
    attn_mma_kernel<<<grid, NTH, SMEM_TOTAL>>>(q, diag, mask, out, attn);
}